// round 11
// baseline (speedup 1.0000x reference)
#include <cuda_runtime.h>
#include <cuda_fp16.h>
#include <math.h>
#include <stdint.h>

#define BATCH 512
#define P 1152
#define NCAPS 10
#define T 16
#define D 8
#define PD 9216          // P*D
#define NT 160           // NCAPS*T
#define KCH1 72          // split-K chunks gemm1 (72*128 = 9216)
#define KCH2 4           // split-K chunks gemm2 (4*128 = 512)

// SMEM stage: K=32 halves (64B/row), 80B row stride.
// A: 128 rows fp16, B: 160 rows fp16
#define SROW 80
#define B_OFF   10240            // 128*80
#define STAGE_BYTES 23040        // + 160*80
#define NSTAGE 4
#define SMEM_BYTES (NSTAGE*STAGE_BYTES)   // 92160 -> 2 CTAs/SM

// ---------------- scratch ----------------------------------------------------
__device__ float  g_Wt2[PD*NT];       // W [pd][nt] fp32 (gemm2 epilogue)
__device__ __half g_Xq[BATCH*PD];     // fl16(X) [b][pd]
__device__ __half g_Xtq[PD*BATCH];    // fl16(X)^T [pd][b]
__device__ __half g_Bq[NT*PD];        // fl16(c.W) [nt][pd]
__device__ __half g_vq[NT*BATCH];     // fl16(v) [nt][b]
__device__ float  g_spart[KCH1*BATCH*NT];
__device__ float  g_bbar[P*NCAPS];
__device__ float  g_b[P*NCAPS];

// ---------------- PTX helpers ------------------------------------------------
__device__ __forceinline__ void mma16816(float* c,
    uint32_t a0, uint32_t a1, uint32_t a2, uint32_t a3,
    uint32_t b0, uint32_t b1) {
    asm volatile(
        "mma.sync.aligned.m16n8k16.row.col.f32.f16.f16.f32 "
        "{%0,%1,%2,%3}, {%4,%5,%6,%7}, {%8,%9}, {%0,%1,%2,%3};"
        : "+f"(c[0]), "+f"(c[1]), "+f"(c[2]), "+f"(c[3])
        : "r"(a0), "r"(a1), "r"(a2), "r"(a3), "r"(b0), "r"(b1));
}
__device__ __forceinline__ void ldmx4(uint32_t* r, uint32_t addr) {
    asm volatile("ldmatrix.sync.aligned.m8n8.x4.shared.b16 {%0,%1,%2,%3}, [%4];"
        : "=r"(r[0]), "=r"(r[1]), "=r"(r[2]), "=r"(r[3]) : "r"(addr));
}
__device__ __forceinline__ void ldmx2(uint32_t* r, uint32_t addr) {
    asm volatile("ldmatrix.sync.aligned.m8n8.x2.shared.b16 {%0,%1}, [%2];"
        : "=r"(r[0]), "=r"(r[1]) : "r"(addr));
}
__device__ __forceinline__ uint32_t s2u(const void* p) {
    uint32_t a;
    asm("{ .reg .u64 t; cvta.to.shared.u64 t, %1; cvt.u32.u64 %0, t; }"
        : "=r"(a) : "l"(p));
    return a;
}
__device__ __forceinline__ void cpasync16(uint32_t dst, const void* src) {
    asm volatile("cp.async.cg.shared.global [%0], [%1], 16;"
        :: "r"(dst), "l"(__cvta_generic_to_global(src)));
}
#define CP_COMMIT() asm volatile("cp.async.commit_group;" ::: "memory")
#define CP_WAIT(n)  asm volatile("cp.async.wait_group %0;" :: "n"(n) : "memory")

__device__ __forceinline__ float red32(float v) {
    #pragma unroll
    for (int o = 16; o > 0; o >>= 1)
        v += __shfl_xor_sync(0xffffffffu, v, o);
    return v;
}

// ---------------- fused prep: W layouts, iter-0 B, X quantize ----------------
#define PREP_WBLOCKS 5760   // NT*PD/256
#define PREP_XBLOCKS 4608   // (PD/32)*(BATCH/32)
__global__ void k_prepall(const float* __restrict__ W, const float* __restrict__ X) {
    if (blockIdx.x < PREP_WBLOCKS) {
        int i = blockIdx.x * 256 + threadIdx.x;
        int nt = i / PD, pd = i - nt*PD;
        int p = pd >> 3, d = pd & 7, n = nt >> 4, t = nt & 15;
        float w = W[((p*NCAPS + n)*T + t)*D + d];
        g_Wt2[(size_t)pd*NT + nt] = w;
        g_Bq[i] = __float2half_rn(0.1f * w);   // iter-0 coupling c = 1/NCAPS
        if (i < P*NCAPS) g_b[i] = 0.0f;
    } else {
        __shared__ __half tb[32][33];
        int bid = blockIdx.x - PREP_WBLOCKS;
        int pd0 = (bid % (PD/32)) * 32, b0 = (bid / (PD/32)) * 32;
        int tx = threadIdx.x & 31, ty = threadIdx.x >> 5;
        #pragma unroll
        for (int j = 0; j < 32; j += 8) {
            float v = X[(size_t)(b0 + ty + j)*PD + pd0 + tx];
            __half h = __float2half_rn(v);
            g_Xq[(size_t)(b0 + ty + j)*PD + pd0 + tx] = h;
            tb[ty + j][tx] = h;
        }
        __syncthreads();
        #pragma unroll
        for (int j = 0; j < 32; j += 8)
            g_Xtq[(size_t)(pd0 + ty + j)*BATCH + b0 + tx] = tb[tx][ty + j];
    }
}

// ---------------- compute one K=32 stage -------------------------------------
// 8 warps as 2(M) x 4(N); warp tile 64(M) x 40(N); pure fp16 operands
__device__ __forceinline__ void compute_stage(
    uint32_t base, int wm64, int wn40, int lane, float acc[4][5][4]) {
    int grp = lane >> 3, lr = lane & 7;
    #pragma unroll
    for (int ko = 0; ko < 32; ko += 16) {
        uint32_t bh[5][2];
        #pragma unroll
        for (int bp = 0; bp < 2; ++bp) {
            uint32_t ba = (uint32_t)((wn40 + bp*16 + ((grp & 2) << 2) + lr)*SROW
                                     + (ko + (grp & 1)*8)*2);
            uint32_t r4[4];
            ldmx4(r4, base + B_OFF + ba);
            bh[bp*2][0]   = r4[0]; bh[bp*2][1]   = r4[1];
            bh[bp*2+1][0] = r4[2]; bh[bp*2+1][1] = r4[3];
        }
        {
            uint32_t ba = (uint32_t)((wn40 + 32 + lr)*SROW + (ko + (grp & 1)*8)*2);
            ldmx2(bh[4], base + B_OFF + ba);
        }
        #pragma unroll
        for (int mt = 0; mt < 4; ++mt) {
            uint32_t aa = (uint32_t)((wm64 + mt*16 + (grp & 1)*8 + lr)*SROW
                                     + (ko + (grp >> 1)*8)*2);
            uint32_t ah[4];
            ldmx4(ah, base + aa);
            #pragma unroll
            for (int bt = 0; bt < 5; ++bt)
                mma16816(acc[mt][bt], ah[0], ah[1], ah[2], ah[3], bh[bt][0], bh[bt][1]);
        }
    }
}

// ---------------- GEMM1: spart[ch] = fl16(X)[128b x 128k] fl16(c.W)[128k x 160]
__global__ void __launch_bounds__(256, 2) k_gemm1() {
    extern __shared__ char smem[];
    uint32_t sb = s2u(smem);
    int tid = threadIdx.x;
    int wid = tid >> 5, lane = tid & 31;
    int wm64 = (wid >> 2) * 64;
    int wn40 = (wid & 3) * 40;
    int b0 = blockIdx.x * 128;
    int kc = blockIdx.y * 128;

    float acc[4][5][4];
    #pragma unroll
    for (int i = 0; i < 4; ++i)
        #pragma unroll
        for (int j = 0; j < 5; ++j)
            #pragma unroll
            for (int r = 0; r < 4; ++r) acc[i][j][r] = 0.0f;

    auto issue = [&](int s, int buf) {
        int kb = kc + s*32;
        uint32_t base = sb + buf*STAGE_BYTES;
        #pragma unroll
        for (int u = 0; u < 2; ++u) {    // A: 128 rows x 4 chunks = 512
            int ch = tid*2 + u, row = ch >> 2, q = ch & 3;
            cpasync16(base + row*SROW + q*16,
                      g_Xq + (size_t)(b0 + row)*PD + kb + q*8);
        }
        #pragma unroll
        for (int u = 0; u < 3; ++u) {    // B: 160 rows x 4 = 640
            int ch = tid + 256*u;
            if (ch < 640) {
                int row = ch >> 2, q = ch & 3;
                cpasync16(base + B_OFF + row*SROW + q*16,
                          g_Bq + (size_t)row*PD + kb + q*8);
            }
        }
    };

    issue(0, 0); CP_COMMIT();
    issue(1, 1); CP_COMMIT();
    issue(2, 2); CP_COMMIT();
    #pragma unroll 1
    for (int s = 0; s < 4; ++s) {
        CP_WAIT(2);
        __syncthreads();
        if (s + 3 < 4) issue(s + 3, s + 3);
        CP_COMMIT();
        compute_stage(sb + (s & 3)*STAGE_BYTES, wm64, wn40, lane, acc);
    }

    int g = lane >> 2, qq = (lane & 3)*2;
    float* out = g_spart + (size_t)blockIdx.y * BATCH * NT;
    #pragma unroll
    for (int mt = 0; mt < 4; ++mt) {
        int row = b0 + wm64 + mt*16 + g;
        #pragma unroll
        for (int bt = 0; bt < 5; ++bt) {
            int col = wn40 + bt*8 + qq;
            *(float2*)&out[(size_t)row*NT + col]       = make_float2(acc[mt][bt][0], acc[mt][bt][1]);
            *(float2*)&out[(size_t)(row + 8)*NT + col] = make_float2(acc[mt][bt][2], acc[mt][bt][3]);
        }
    }
}

// ---------------- GEMM2 + fused agreement epilogue ---------------------------
__global__ void __launch_bounds__(256, 2) k_gemm2() {
    extern __shared__ char smem[];
    uint32_t sb = s2u(smem);
    int tid = threadIdx.x;
    int wid = tid >> 5, lane = tid & 31;
    int wm64 = (wid >> 2) * 64;
    int wn40 = (wid & 3) * 40;
    int pd0 = blockIdx.x * 128;
    int kc = blockIdx.y * 128;

    float acc[4][5][4];
    #pragma unroll
    for (int i = 0; i < 4; ++i)
        #pragma unroll
        for (int j = 0; j < 5; ++j)
            #pragma unroll
            for (int r = 0; r < 4; ++r) acc[i][j][r] = 0.0f;

    auto issue = [&](int s, int buf) {
        int kb = kc + s*32;
        uint32_t base = sb + buf*STAGE_BYTES;
        #pragma unroll
        for (int u = 0; u < 2; ++u) {    // A: 128 pd-rows x 4 chunks
            int ch = tid*2 + u, row = ch >> 2, q = ch & 3;
            cpasync16(base + row*SROW + q*16,
                      g_Xtq + (size_t)(pd0 + row)*BATCH + kb + q*8);
        }
        #pragma unroll
        for (int u = 0; u < 3; ++u) {    // B: 160 nt-rows x 4
            int ch = tid + 256*u;
            if (ch < 640) {
                int row = ch >> 2, q = ch & 3;
                cpasync16(base + B_OFF + row*SROW + q*16,
                          g_vq + (size_t)row*BATCH + kb + q*8);
            }
        }
    };

    issue(0, 0); CP_COMMIT();
    issue(1, 1); CP_COMMIT();
    issue(2, 2); CP_COMMIT();
    #pragma unroll 1
    for (int s = 0; s < 4; ++s) {
        CP_WAIT(2);
        __syncthreads();
        if (s + 3 < 4) issue(s + 3, s + 3);
        CP_COMMIT();
        compute_stage(sb + (s & 3)*STAGE_BYTES, wm64, wn40, lane, acc);
    }

    int g = lane >> 2, qq = (lane & 3)*2;
    // Fused agreement: bbar[p][n] += W (.) acc summed over d (rows) and t (cols).
    // Group bt-fragments by shared n, full-warp reduce, lane-0 REDG.
    #pragma unroll
    for (int mt = 0; mt < 4; ++mt) {
        int r0 = wm64 + mt*16 + g;
        int pg = (pd0 + wm64 + mt*16) >> 3;     // global p of rows [r0 block]
        float v0 = 0.0f, v1 = 0.0f;
        int curn = wn40 >> 4;
        #pragma unroll
        for (int bt = 0; bt < 5; ++bt) {
            int colb = wn40 + bt*8;
            int n = colb >> 4;
            if (n != curn) {                     // warp-uniform branch
                float s0 = red32(v0), s1 = red32(v1);
                if (lane == 0) {
                    atomicAdd(&g_bbar[pg*NCAPS + curn], s0);
                    atomicAdd(&g_bbar[(pg + 1)*NCAPS + curn], s1);
                }
                v0 = v1 = 0.0f;
                curn = n;
            }
            int col = colb + qq;
            float2 w0 = *(const float2*)&g_Wt2[(size_t)(pd0 + r0)*NT + col];
            float2 w1 = *(const float2*)&g_Wt2[(size_t)(pd0 + r0 + 8)*NT + col];
            v0 += acc[mt][bt][0]*w0.x + acc[mt][bt][1]*w0.y;
            v1 += acc[mt][bt][2]*w1.x + acc[mt][bt][3]*w1.y;
        }
        {
            float s0 = red32(v0), s1 = red32(v1);
            if (lane == 0) {
                atomicAdd(&g_bbar[pg*NCAPS + curn], s0);
                atomicAdd(&g_bbar[(pg + 1)*NCAPS + curn], s1);
            }
        }
    }
}

// ---------------- fused reduce + squash (float4; zero bbar) ------------------
__global__ void k_redsquash(float* __restrict__ out, int final_it) {
    int i4 = blockIdx.x * blockDim.x + threadIdx.x;   // [0, BATCH*NT/4)
    const float4* sp = (const float4*)g_spart;
    float4 s = make_float4(0.0f, 0.0f, 0.0f, 0.0f);
    #pragma unroll
    for (int ch = 0; ch < KCH1; ++ch) {
        float4 t = sp[(size_t)ch*(BATCH*NT/4) + i4];
        s.x += t.x; s.y += t.y; s.z += t.z; s.w += t.w;
    }
    float ss = s.x*s.x + s.y*s.y + s.z*s.z + s.w*s.w;
    #pragma unroll
    for (int o = 1; o < 4; o <<= 1)
        ss += __shfl_xor_sync(0xffffffffu, ss, o);    // 4 lanes x 4 = 16 t's
    float nrm = sqrtf(ss);
    float f = ss / (1.0f + ss*(nrm + 1e-9f));
    float4 v = make_float4(f*s.x, f*s.y, f*s.z, f*s.w);
    if (final_it) {
        ((float4*)out)[i4] = v;
    } else {
        int idx = 4*i4;
        int b = idx / NT, nt = idx - b*NT;
        g_vq[(size_t)nt*BATCH + b]     = __float2half_rn(v.x);
        g_vq[(size_t)(nt+1)*BATCH + b] = __float2half_rn(v.y);
        g_vq[(size_t)(nt+2)*BATCH + b] = __float2half_rn(v.z);
        g_vq[(size_t)(nt+3)*BATCH + b] = __float2half_rn(v.w);
        if (i4 < P*NCAPS/4)
            ((float4*)g_bbar)[i4] = make_float4(0.0f, 0.0f, 0.0f, 0.0f);
    }
}

// ---------------- fused route (softmax) + B quantize -------------------------
// 144 blocks x 256 threads; block owns pd range [blk*64, +64) = 8 p's
__global__ void __launch_bounds__(256) k_routesplitB(const float* __restrict__ W) {
    __shared__ float sbn[8][10];
    __shared__ float sc[8][10];
    int tid = threadIdx.x;
    int p0 = blockIdx.x * 8;
    int pd0 = blockIdx.x * 64;

    if (tid < 80) {
        int lp = tid / 10, n = tid - lp*10;
        int p = p0 + lp;
        float bn = g_b[p*NCAPS + n] + g_bbar[p*NCAPS + n] * (1.0f / (float)BATCH);
        g_b[p*NCAPS + n] = bn;
        sbn[lp][n] = bn;
    }
    __syncthreads();
    if (tid < 8) {
        float mx = -1e30f;
        #pragma unroll
        for (int n = 0; n < NCAPS; ++n) mx = fmaxf(mx, sbn[tid][n]);
        float sum = 0.0f;
        float e[NCAPS];
        #pragma unroll
        for (int n = 0; n < NCAPS; ++n) { e[n] = expf(sbn[tid][n] - mx); sum += e[n]; }
        float rs = 1.0f / sum;
        #pragma unroll
        for (int n = 0; n < NCAPS; ++n) sc[tid][n] = e[n]*rs;
    }
    __syncthreads();

    #pragma unroll
    for (int u = 0; u < 10; ++u) {
        int fl = tid + 256*u;          // 0..2559: 160 nt x 16 pd-quads
        int nt = fl >> 4, pdq = fl & 15;
        int n = nt >> 4, t = nt & 15;
        int p = p0 + (pdq >> 1), d0 = (pdq & 1)*4;
        float c = sc[pdq >> 1][n];
        float4 w = *(const float4*)&W[((p*NCAPS + n)*T + t)*D + d0];
        size_t base = (size_t)nt*PD + pd0 + pdq*4;
        *(__half2*)&g_Bq[base]     = __floats2half2_rn(w.x*c, w.y*c);
        *(__half2*)&g_Bq[base + 2] = __floats2half2_rn(w.z*c, w.w*c);
    }
}

// ---------------- launch -----------------------------------------------------
extern "C" void kernel_launch(void* const* d_in, const int* in_sizes, int n_in,
                              void* d_out, int out_size) {
    (void)in_sizes; (void)n_in; (void)out_size;
    const float* x = (const float*)d_in[0];   // [512, 1152, 8]
    const float* W = (const float*)d_in[1];   // [1152, 10, 16, 8]
    float* out = (float*)d_out;               // [512, 10, 16, 1]

    cudaFuncSetAttribute((const void*)k_gemm1,
                         cudaFuncAttributeMaxDynamicSharedMemorySize, SMEM_BYTES);
    cudaFuncSetAttribute((const void*)k_gemm2,
                         cudaFuncAttributeMaxDynamicSharedMemorySize, SMEM_BYTES);

    k_prepall<<<PREP_WBLOCKS + PREP_XBLOCKS, 256>>>(W, x);

    for (int it = 0; it < 3; ++it) {
        k_gemm1<<<dim3(BATCH/128, KCH1), 256, SMEM_BYTES>>>();
        k_redsquash<<<(BATCH*NT/4)/128, 128>>>(out, it == 2 ? 1 : 0);
        if (it < 2) {
            k_gemm2<<<dim3(PD/128, KCH2), 256, SMEM_BYTES>>>();
            k_routesplitB<<<P/8, 256>>>(W);
        }
    }
}

// round 12
// speedup vs baseline: 1.3082x; 1.3082x over previous
#include <cuda_runtime.h>
#include <cuda_fp16.h>
#include <math.h>
#include <stdint.h>

#define BATCH 512
#define P 1152
#define NCAPS 10
#define T 16
#define D 8
#define PD 9216          // P*D
#define NT 160           // NCAPS*T
#define KCH1 36          // split-K chunks gemm1 (36*256 = 9216)
#define KCH2 2           // split-K chunks gemm2 (2*256 = 512)

// SMEM stage: K=32 halves (64B/row), 80B row stride.
// A: 64 rows fp16, B: 160 rows fp16
#define SROW 80
#define B_OFF   5120             // 64*80
#define STAGE_BYTES 17920        // + 160*80
#define NSTAGE 4
#define SMEM_BYTES (NSTAGE*STAGE_BYTES)   // 71680 -> 2 CTAs/SM

// ---------------- scratch ----------------------------------------------------
__device__ float  g_Wt2[PD*NT];       // W [pd][nt] fp32 (gemm2 epilogue)
__device__ __half g_Xq[BATCH*PD];     // fl16(X) [b][pd]
__device__ __half g_Xtq[PD*BATCH];    // fl16(X)^T [pd][b]
__device__ __half g_Bq[NT*PD];        // fl16(c.W) [nt][pd]
__device__ __half g_vq[NT*BATCH];     // fl16(v) [nt][b]
__device__ float  g_spart[KCH1*BATCH*NT];
__device__ float  g_bbar[P*NCAPS];
__device__ float  g_b[P*NCAPS];

// ---------------- PTX helpers ------------------------------------------------
__device__ __forceinline__ void mma16816(float* c,
    uint32_t a0, uint32_t a1, uint32_t a2, uint32_t a3,
    uint32_t b0, uint32_t b1) {
    asm volatile(
        "mma.sync.aligned.m16n8k16.row.col.f32.f16.f16.f32 "
        "{%0,%1,%2,%3}, {%4,%5,%6,%7}, {%8,%9}, {%0,%1,%2,%3};"
        : "+f"(c[0]), "+f"(c[1]), "+f"(c[2]), "+f"(c[3])
        : "r"(a0), "r"(a1), "r"(a2), "r"(a3), "r"(b0), "r"(b1));
}
__device__ __forceinline__ void ldmx4(uint32_t* r, uint32_t addr) {
    asm volatile("ldmatrix.sync.aligned.m8n8.x4.shared.b16 {%0,%1,%2,%3}, [%4];"
        : "=r"(r[0]), "=r"(r[1]), "=r"(r[2]), "=r"(r[3]) : "r"(addr));
}
__device__ __forceinline__ void ldmx2(uint32_t* r, uint32_t addr) {
    asm volatile("ldmatrix.sync.aligned.m8n8.x2.shared.b16 {%0,%1}, [%2];"
        : "=r"(r[0]), "=r"(r[1]) : "r"(addr));
}
__device__ __forceinline__ uint32_t s2u(const void* p) {
    uint32_t a;
    asm("{ .reg .u64 t; cvta.to.shared.u64 t, %1; cvt.u32.u64 %0, t; }"
        : "=r"(a) : "l"(p));
    return a;
}
__device__ __forceinline__ void cpasync16(uint32_t dst, const void* src) {
    asm volatile("cp.async.cg.shared.global [%0], [%1], 16;"
        :: "r"(dst), "l"(__cvta_generic_to_global(src)));
}
#define CP_COMMIT() asm volatile("cp.async.commit_group;" ::: "memory")
#define CP_WAIT(n)  asm volatile("cp.async.wait_group %0;" :: "n"(n) : "memory")

__device__ __forceinline__ float red32(float v) {
    #pragma unroll
    for (int o = 16; o > 0; o >>= 1)
        v += __shfl_xor_sync(0xffffffffu, v, o);
    return v;
}

// ---------------- fused prep -------------------------------------------------
// W-part: 360 tiled blocks (16 nt x 256 pd), smem transpose, sector-efficient.
// X-part: 4608 blocks (32x32 transpose tiles), as before.
#define PREP_WBLOCKS 360
#define PREP_XBLOCKS 4608
__global__ void __launch_bounds__(256) k_prepall(
    const float* __restrict__ W, const float* __restrict__ X) {
    int tid = threadIdx.x;
    if (blockIdx.x < PREP_WBLOCKS) {
        __shared__ float ts[256][20];      // [pd_local][t]
        int tb = blockIdx.x;
        int n  = tb / 36;                  // nt tile == one n (16 t's)
        int pd0 = (tb % 36) * 256;
        int p0 = pd0 >> 3;

        if (tb*256 + tid < P*NCAPS) g_b[tb*256 + tid] = 0.0f;

        // read W: 32 p-chunks x 128 contiguous floats (t,d block), float4
        {
            int chunk = tid >> 3, inner = tid & 7;
            const float* src = W + (size_t)(p0 + chunk)*(NCAPS*T*D) + n*(T*D)
                               + inner*16;
            #pragma unroll
            for (int j4 = 0; j4 < 4; ++j4) {
                float4 v = *(const float4*)(src + j4*4);
                int l0 = inner*16 + j4*4;
                int t = l0 >> 3, d = l0 & 7;
                ts[chunk*8 + d    ][t] = v.x;
                ts[chunk*8 + d + 1][t] = v.y;
                ts[chunk*8 + d + 2][t] = v.z;
                ts[chunk*8 + d + 3][t] = v.w;
            }
        }
        __syncthreads();
        // Wt2 [pd][nt]: aligned float4 stores
        {
            int lane4 = tid & 3, rbase = tid >> 2;
            #pragma unroll
            for (int rr = 0; rr < 4; ++rr) {
                int row = rbase + rr*64;
                float4 v = *(const float4*)&ts[row][lane4*4];
                *(float4*)&g_Wt2[(size_t)(pd0 + row)*NT + n*16 + lane4*4] = v;
            }
        }
        // Bq [nt][pd]: 32B (sector-exact) per thread
        {
            int ntl = tid & 15, pdl = (tid >> 4) * 16;
            __half hbuf[16];
            #pragma unroll
            for (int j = 0; j < 16; ++j)
                hbuf[j] = __float2half_rn(0.1f * ts[pdl + j][ntl]);
            uint4* dst = (uint4*)&g_Bq[(size_t)(n*16 + ntl)*PD + pd0 + pdl];
            dst[0] = *(uint4*)&hbuf[0];
            dst[1] = *(uint4*)&hbuf[8];
        }
    } else {
        __shared__ __half tb2[32][33];
        int bid = blockIdx.x - PREP_WBLOCKS;
        int pd0 = (bid % (PD/32)) * 32, b0 = (bid / (PD/32)) * 32;
        int tx = tid & 31, ty = tid >> 5;
        #pragma unroll
        for (int j = 0; j < 32; j += 8) {
            float v = X[(size_t)(b0 + ty + j)*PD + pd0 + tx];
            __half h = __float2half_rn(v);
            g_Xq[(size_t)(b0 + ty + j)*PD + pd0 + tx] = h;
            tb2[ty + j][tx] = h;
        }
        __syncthreads();
        #pragma unroll
        for (int j = 0; j < 32; j += 8)
            g_Xtq[(size_t)(pd0 + ty + j)*BATCH + b0 + tx] = tb2[tx][ty + j];
    }
}

// ---------------- compute one K=32 stage -------------------------------------
// 8 warps as 2(M) x 4(N); warp tile 32(M) x 40(N); pure fp16 operands
__device__ __forceinline__ void compute_stage(
    uint32_t base, int wm32, int wn40, int lane, float acc[2][5][4]) {
    int grp = lane >> 3, lr = lane & 7;
    #pragma unroll
    for (int ko = 0; ko < 32; ko += 16) {
        uint32_t bh[5][2];
        #pragma unroll
        for (int bp = 0; bp < 2; ++bp) {
            uint32_t ba = (uint32_t)((wn40 + bp*16 + ((grp & 2) << 2) + lr)*SROW
                                     + (ko + (grp & 1)*8)*2);
            uint32_t r4[4];
            ldmx4(r4, base + B_OFF + ba);
            bh[bp*2][0]   = r4[0]; bh[bp*2][1]   = r4[1];
            bh[bp*2+1][0] = r4[2]; bh[bp*2+1][1] = r4[3];
        }
        {
            uint32_t ba = (uint32_t)((wn40 + 32 + lr)*SROW + (ko + (grp & 1)*8)*2);
            ldmx2(bh[4], base + B_OFF + ba);
        }
        #pragma unroll
        for (int mt = 0; mt < 2; ++mt) {
            uint32_t aa = (uint32_t)((wm32 + mt*16 + (grp & 1)*8 + lr)*SROW
                                     + (ko + (grp >> 1)*8)*2);
            uint32_t ah[4];
            ldmx4(ah, base + aa);
            #pragma unroll
            for (int bt = 0; bt < 5; ++bt)
                mma16816(acc[mt][bt], ah[0], ah[1], ah[2], ah[3], bh[bt][0], bh[bt][1]);
        }
    }
}

// ---------------- GEMM1: spart[ch] = fl16(X)[64b x 256k] fl16(c.W)[256k x 160]
__global__ void __launch_bounds__(256, 2) k_gemm1() {
    extern __shared__ char smem[];
    uint32_t sb = s2u(smem);
    int tid = threadIdx.x;
    int wid = tid >> 5, lane = tid & 31;
    int wm32 = (wid >> 2) * 32;
    int wn40 = (wid & 3) * 40;
    int b0 = blockIdx.x * 64;
    int kc = blockIdx.y * 256;

    float acc[2][5][4];
    #pragma unroll
    for (int i = 0; i < 2; ++i)
        #pragma unroll
        for (int j = 0; j < 5; ++j)
            #pragma unroll
            for (int r = 0; r < 4; ++r) acc[i][j][r] = 0.0f;

    auto issue = [&](int s, int buf) {
        int kb = kc + s*32;
        uint32_t base = sb + buf*STAGE_BYTES;
        {   // A: 64 rows x 4 chunks = 256, 1/thread
            int row = tid >> 2, q = tid & 3;
            cpasync16(base + row*SROW + q*16,
                      g_Xq + (size_t)(b0 + row)*PD + kb + q*8);
        }
        #pragma unroll
        for (int u = 0; u < 3; ++u) {   // B: 160 rows x 4 = 640
            int ch = tid + 256*u;
            if (ch < 640) {
                int row = ch >> 2, q = ch & 3;
                cpasync16(base + B_OFF + row*SROW + q*16,
                          g_Bq + (size_t)row*PD + kb + q*8);
            }
        }
    };

    issue(0, 0); CP_COMMIT();
    issue(1, 1); CP_COMMIT();
    issue(2, 2); CP_COMMIT();
    #pragma unroll 1
    for (int s = 0; s < 8; ++s) {
        CP_WAIT(2);
        __syncthreads();
        if (s + 3 < 8) issue(s + 3, (s + 3) & 3);
        CP_COMMIT();
        compute_stage(sb + (s & 3)*STAGE_BYTES, wm32, wn40, lane, acc);
    }

    int g = lane >> 2, qq = (lane & 3)*2;
    float* out = g_spart + (size_t)blockIdx.y * BATCH * NT;
    #pragma unroll
    for (int mt = 0; mt < 2; ++mt) {
        int row = b0 + wm32 + mt*16 + g;
        #pragma unroll
        for (int bt = 0; bt < 5; ++bt) {
            int col = wn40 + bt*8 + qq;
            *(float2*)&out[(size_t)row*NT + col]       = make_float2(acc[mt][bt][0], acc[mt][bt][1]);
            *(float2*)&out[(size_t)(row + 8)*NT + col] = make_float2(acc[mt][bt][2], acc[mt][bt][3]);
        }
    }
}

// ---------------- GEMM2 + fused agreement epilogue ---------------------------
// Wt2 tile (64 pd x 160 floats = 40960B) prefetched via cp.async into the
// retired stage buffers (buf0 at s==5, buf1 at s==6, buf2 head at s==7).
__global__ void __launch_bounds__(256, 2) k_gemm2() {
    extern __shared__ char smem[];
    uint32_t sb = s2u(smem);
    int tid = threadIdx.x;
    int wid = tid >> 5, lane = tid & 31;
    int wm32 = (wid >> 2) * 32;
    int wn40 = (wid & 3) * 40;
    int pd0 = blockIdx.x * 64;
    int kc = blockIdx.y * 256;

    float acc[2][5][4];
    #pragma unroll
    for (int i = 0; i < 2; ++i)
        #pragma unroll
        for (int j = 0; j < 5; ++j)
            #pragma unroll
            for (int r = 0; r < 4; ++r) acc[i][j][r] = 0.0f;

    auto issue = [&](int s, int buf) {
        int kb = kc + s*32;
        uint32_t base = sb + buf*STAGE_BYTES;
        {
            int row = tid >> 2, q = tid & 3;
            cpasync16(base + row*SROW + q*16,
                      g_Xtq + (size_t)(pd0 + row)*BATCH + kb + q*8);
        }
        #pragma unroll
        for (int u = 0; u < 3; ++u) {
            int ch = tid + 256*u;
            if (ch < 640) {
                int row = ch >> 2, q = ch & 3;
                cpasync16(base + B_OFF + row*SROW + q*16,
                          g_vq + (size_t)row*BATCH + kb + q*8);
            }
        }
    };
    // copy 1/3 of the Wt2 tile into smem bytes [part*17920 ...)
    auto issue_wt2 = [&](int part) {
        #pragma unroll
        for (int u = 0; u < 5; ++u) {
            int ch = part*1120 + tid + 256*u;
            if (ch < (part + 1)*1120 && ch < 2560) {   // 2560 x 16B = 40960B
                int row = ch / 40, c16 = ch % 40;      // 160 floats = 40 chunks/row
                cpasync16(sb + ch*16,
                          g_Wt2 + (size_t)(pd0 + row)*NT + c16*4);
            }
        }
    };

    issue(0, 0); CP_COMMIT();
    issue(1, 1); CP_COMMIT();
    issue(2, 2); CP_COMMIT();
    #pragma unroll 1
    for (int s = 0; s < 8; ++s) {
        CP_WAIT(2);
        __syncthreads();
        if (s + 3 < 8) issue(s + 3, (s + 3) & 3);
        else           issue_wt2(s - 5);
        CP_COMMIT();
        compute_stage(sb + (s & 3)*STAGE_BYTES, wm32, wn40, lane, acc);
    }
    CP_WAIT(0);
    __syncthreads();

    const float* wt = (const float*)smem;    // Wt2 tile [64][160]
    int g = lane >> 2, qq = (lane & 3)*2;
    // fused agreement: bbar[p][n] += W (.) acc, grouped by n, warp-reduced
    #pragma unroll
    for (int mt = 0; mt < 2; ++mt) {
        int r0 = wm32 + mt*16 + g;
        int pg = (pd0 + wm32 + mt*16) >> 3;
        float v0 = 0.0f, v1 = 0.0f;
        int curn = wn40 >> 4;
        #pragma unroll
        for (int bt = 0; bt < 5; ++bt) {
            int colb = wn40 + bt*8;
            int n = colb >> 4;
            if (n != curn) {                     // warp-uniform branch
                float s0 = red32(v0), s1 = red32(v1);
                if (lane == 0) {
                    atomicAdd(&g_bbar[pg*NCAPS + curn], s0);
                    atomicAdd(&g_bbar[(pg + 1)*NCAPS + curn], s1);
                }
                v0 = v1 = 0.0f;
                curn = n;
            }
            int col = colb + qq;
            float2 w0 = *(const float2*)&wt[r0*NT + col];
            float2 w1 = *(const float2*)&wt[(r0 + 8)*NT + col];
            v0 += acc[mt][bt][0]*w0.x + acc[mt][bt][1]*w0.y;
            v1 += acc[mt][bt][2]*w1.x + acc[mt][bt][3]*w1.y;
        }
        {
            float s0 = red32(v0), s1 = red32(v1);
            if (lane == 0) {
                atomicAdd(&g_bbar[pg*NCAPS + curn], s0);
                atomicAdd(&g_bbar[(pg + 1)*NCAPS + curn], s1);
            }
        }
    }
}

// ---------------- fused reduce + squash (float4; zero bbar) ------------------
__global__ void k_redsquash(float* __restrict__ out, int final_it) {
    int i4 = blockIdx.x * blockDim.x + threadIdx.x;   // [0, BATCH*NT/4)
    const float4* sp = (const float4*)g_spart;
    float4 s = make_float4(0.0f, 0.0f, 0.0f, 0.0f);
    #pragma unroll
    for (int ch = 0; ch < KCH1; ++ch) {
        float4 t = sp[(size_t)ch*(BATCH*NT/4) + i4];
        s.x += t.x; s.y += t.y; s.z += t.z; s.w += t.w;
    }
    float ss = s.x*s.x + s.y*s.y + s.z*s.z + s.w*s.w;
    #pragma unroll
    for (int o = 1; o < 4; o <<= 1)
        ss += __shfl_xor_sync(0xffffffffu, ss, o);    // 4 lanes x 4 = 16 t's
    float nrm = sqrtf(ss);
    float f = ss / (1.0f + ss*(nrm + 1e-9f));
    float4 v = make_float4(f*s.x, f*s.y, f*s.z, f*s.w);
    if (final_it) {
        ((float4*)out)[i4] = v;
    } else {
        int idx = 4*i4;
        int b = idx / NT, nt = idx - b*NT;
        g_vq[(size_t)nt*BATCH + b]     = __float2half_rn(v.x);
        g_vq[(size_t)(nt+1)*BATCH + b] = __float2half_rn(v.y);
        g_vq[(size_t)(nt+2)*BATCH + b] = __float2half_rn(v.z);
        g_vq[(size_t)(nt+3)*BATCH + b] = __float2half_rn(v.w);
        if (i4 < P*NCAPS/4)
            ((float4*)g_bbar)[i4] = make_float4(0.0f, 0.0f, 0.0f, 0.0f);
    }
}

// ---------------- fused route (softmax) + B quantize -------------------------
// 144 blocks x 256 threads; block owns pd range [blk*64, +64) = 8 p's
__global__ void __launch_bounds__(256) k_routesplitB(const float* __restrict__ W) {
    __shared__ float sbn[8][10];
    __shared__ float sc[8][10];
    int tid = threadIdx.x;
    int p0 = blockIdx.x * 8;
    int pd0 = blockIdx.x * 64;

    if (tid < 80) {
        int lp = tid / 10, n = tid - lp*10;
        int p = p0 + lp;
        float bn = g_b[p*NCAPS + n] + g_bbar[p*NCAPS + n] * (1.0f / (float)BATCH);
        g_b[p*NCAPS + n] = bn;
        sbn[lp][n] = bn;
    }
    __syncthreads();
    if (tid < 8) {
        float mx = -1e30f;
        #pragma unroll
        for (int n = 0; n < NCAPS; ++n) mx = fmaxf(mx, sbn[tid][n]);
        float sum = 0.0f;
        float e[NCAPS];
        #pragma unroll
        for (int n = 0; n < NCAPS; ++n) { e[n] = expf(sbn[tid][n] - mx); sum += e[n]; }
        float rs = 1.0f / sum;
        #pragma unroll
        for (int n = 0; n < NCAPS; ++n) sc[tid][n] = e[n]*rs;
    }
    __syncthreads();

    #pragma unroll
    for (int u = 0; u < 10; ++u) {
        int fl = tid + 256*u;          // 0..2559: 160 nt x 16 pd-quads
        int nt = fl >> 4, pdq = fl & 15;
        int n = nt >> 4, t = nt & 15;
        int p = p0 + (pdq >> 1), d0 = (pdq & 1)*4;
        float c = sc[pdq >> 1][n];
        float4 w = *(const float4*)&W[((p*NCAPS + n)*T + t)*D + d0];
        size_t base = (size_t)nt*PD + pd0 + pdq*4;
        *(__half2*)&g_Bq[base]     = __floats2half2_rn(w.x*c, w.y*c);
        *(__half2*)&g_Bq[base + 2] = __floats2half2_rn(w.z*c, w.w*c);
    }
}

// ---------------- launch -----------------------------------------------------
extern "C" void kernel_launch(void* const* d_in, const int* in_sizes, int n_in,
                              void* d_out, int out_size) {
    (void)in_sizes; (void)n_in; (void)out_size;
    const float* x = (const float*)d_in[0];   // [512, 1152, 8]
    const float* W = (const float*)d_in[1];   // [1152, 10, 16, 8]
    float* out = (float*)d_out;               // [512, 10, 16, 1]

    cudaFuncSetAttribute((const void*)k_gemm1,
                         cudaFuncAttributeMaxDynamicSharedMemorySize, SMEM_BYTES);
    cudaFuncSetAttribute((const void*)k_gemm2,
                         cudaFuncAttributeMaxDynamicSharedMemorySize, SMEM_BYTES);

    k_prepall<<<PREP_WBLOCKS + PREP_XBLOCKS, 256>>>(W, x);

    for (int it = 0; it < 3; ++it) {
        k_gemm1<<<dim3(BATCH/64, KCH1), 256, SMEM_BYTES>>>();
        k_redsquash<<<(BATCH*NT/4)/128, 128>>>(out, it == 2 ? 1 : 0);
        if (it < 2) {
            k_gemm2<<<dim3(PD/64, KCH2), 256, SMEM_BYTES>>>();
            k_routesplitB<<<P/8, 256>>>(W);
        }
    }
}